// round 15
// baseline (speedup 1.0000x reference)
#include <cuda_runtime.h>
#include <math.h>

#define EMB 256
#define VOCAB 50000
#define ROWS_OUT 101
#define BN_EPS 1e-5f
#define NLSTM 8
#define NY 4
#define NXT 196
#define HT_STRIDE 104

// ---------------- packed f32x2 helpers ----------------
#define FMA2(acc, a, b) \
    asm("fma.rn.f32x2 %0, %1, %2, %0;" : "+l"(acc) : "l"(a), "l"(b))
#define ADD2(acc, b) \
    asm("add.rn.f32x2 %0, %0, %1;" : "+l"(acc) : "l"(b))
#define UNPACK64(lo, hi, v) do { unsigned _ulo, _uhi; \
    asm("mov.b64 {%0, %1}, %2;" : "=r"(_ulo), "=r"(_uhi) : "l"(v)); \
    lo = __uint_as_float(_ulo); hi = __uint_as_float(_uhi); } while (0)
#define DUP2(d, f) do { unsigned _u = __float_as_uint(f); \
    asm("mov.b64 %0, {%1, %1};" : "=l"(d) : "r"(_u)); } while (0)

// ---------------- device scratch ----------------
__device__ float g_d1[384];               // conv output (361 used, rest 0)
__device__ float g_feat[EMB];
__device__ float g_Ht[EMB * HT_STRIDE];   // transposed H: [k][step]
__device__ int g_flag[NY];
__device__ int g_dflag;

// ---------------- K1: grid of 9 CTAs ----------------
__device__ __forceinline__ void block_sum2(float& a, float& b,
                                           float* redA, float* redB) {
#pragma unroll
    for (int o = 16; o; o >>= 1) {
        a += __shfl_xor_sync(0xffffffffu, a, o);
        b += __shfl_xor_sync(0xffffffffu, b, o);
    }
    __syncthreads();
    if ((threadIdx.x & 31) == 0) {
        redA[threadIdx.x >> 5] = a;
        redB[threadIdx.x >> 5] = b;
    }
    __syncthreads();
    float sa = 0.f, sb = 0.f;
#pragma unroll
    for (int i = 0; i < 16; i++) { sa += redA[i]; sb += redB[i]; }
    a = sa; b = sb;
}

__global__ void k1_prep(const float* __restrict__ board,
                        const float* __restrict__ conv_w,
                        const float* __restrict__ conv_b,
                        const float* __restrict__ bn_gamma,
                        const float* __restrict__ bn_beta,
                        const float* __restrict__ p,
                        const float* __restrict__ Wlin,
                        const float* __restrict__ b_lin) {
    extern __shared__ __align__(16) float k1sm[];
    __shared__ float A[441];
    __shared__ float B[441];
    __shared__ float d2s[361];
    __shared__ float redA[16];
    __shared__ float redB[16];

    int tid = threadIdx.x;
    int bid = blockIdx.x;

    if (bid == 0) {
        if (tid < NY) g_flag[tid] = 0;

        float w[9];
#pragma unroll
        for (int q = 0; q < 9; q++) w[q] = conv_w[q];
        float cbias = conv_b[0], gamma = bn_gamma[0], beta = bn_beta[0];

        if (tid < 441) { A[tid] = 0.f; B[tid] = 0.f; }
        __syncthreads();
        if (tid < 361) {
            int r = tid / 19, c = tid % 19;
            A[(r + 1) * 21 + (c + 1)] = board[tid];
        }
        __syncthreads();

        float* src = A;
        float* dst = B;
        const int types[8] = {0, 0, 1, 0, 1, 0, 1, 2};
        const int pidx[8]  = {0, 1, 2, 3, 4, 5, 6, 0};

        for (int st = 0; st < 8; st++) {
            float y = 0.f;
            int base = 0;
            if (tid < 361) {
                int r = tid / 19, c = tid % 19;
                base = (r + 1) * 21 + (c + 1);
#pragma unroll
                for (int ki = 0; ki < 3; ki++)
#pragma unroll
                    for (int kj = 0; kj < 3; kj++)
                        y += w[ki * 3 + kj] * src[base + (ki - 1) * 21 + (kj - 1)];
                y += cbias;
            }
            float s1 = (tid < 361) ? y : 0.f;
            float s2 = s1 * s1;
            block_sum2(s1, s2, redA, redB);
            float mu = s1 * (1.f / 361.f);
            float var = s2 * (1.f / 361.f) - mu * mu;
            float rstd = rsqrtf(var + BN_EPS);

            if (tid < 361) {
                float z = gamma * (y - mu) * rstd + beta;
                float v;
                int t = types[st];
                if (t == 0)      v = fmaxf(p[pidx[st]] * z, 0.f);
                else if (t == 1) v = fmaxf(p[pidx[st]] * z + d2s[tid], 0.f);
                else             v = fmaxf(z, 0.f);
                dst[base] = v;
                if (st == 0 || t == 1) d2s[tid] = v;
            }
            __syncthreads();
            float* tmp = src; src = dst; dst = tmp;
        }

        if (tid < 384) {
            float v = 0.f;
            if (tid < 361) {
                int r = tid / 19, c = tid % 19;
                v = src[(r + 1) * 21 + (c + 1)];
            }
            g_d1[tid] = v;
        }
        __syncthreads();
        if (tid == 0) {
            __threadfence();
            atomicExch(&g_dflag, 1);
        }
    } else {
        float* d1s = k1sm;            // 384
        float* ws  = k1sm + 384;      // 32 * 361

        int ebase = (bid - 1) * 32;
        for (int idx = tid; idx < 32 * 361; idx += 512)
            ws[idx] = Wlin[ebase * 361 + idx];

        if (tid == 0) {
            while (atomicAdd(&g_dflag, 0) == 0) __nanosleep(64);
        }
        __syncthreads();
        __threadfence();
        for (int i = tid; i < 384; i += 512) d1s[i] = g_d1[i];
        __syncthreads();

        int wi = tid >> 5, lane = tid & 31;
        const float* r0 = ws + (2 * wi) * 361;
        const float* r1 = ws + (2 * wi + 1) * 361;
        float a0 = 0.f, a1 = 0.f;
#pragma unroll
        for (int t = 0; t < 12; t++) {
            int j = lane + 32 * t;
            if (j < 361) {
                float d = d1s[j];
                a0 += r0[j] * d;
                a1 += r1[j] * d;
            }
        }
#pragma unroll
        for (int m = 16; m; m >>= 1) {
            a0 += __shfl_xor_sync(0xffffffffu, a0, m);
            a1 += __shfl_xor_sync(0xffffffffu, a1, m);
        }
        if (lane < 2) {
            int e = ebase + 2 * wi + lane;
            float v = (lane == 0) ? a0 : a1;
            g_feat[e] = v + b_lin[e];
        }
    }
}

// ---------------- cluster / mbarrier helpers ----------------
__device__ __forceinline__ void cluster_sync_() {
    asm volatile("barrier.cluster.arrive.aligned;" ::: "memory");
    asm volatile("barrier.cluster.wait.aligned;" ::: "memory");
}
__device__ __forceinline__ unsigned smem_u32(const void* p) {
    unsigned a;
    asm("{ .reg .u64 t; cvta.to.shared.u64 t, %1; cvt.u32.u64 %0, t; }"
        : "=r"(a) : "l"(p));
    return a;
}
__device__ __forceinline__ void mbar_init_(unsigned addr, unsigned cnt) {
    asm volatile("mbarrier.init.shared.b64 [%0], %1;" :: "r"(addr), "r"(cnt) : "memory");
}
__device__ __forceinline__ void mbar_arrive_expect(unsigned addr, unsigned tx) {
    asm volatile("mbarrier.arrive.expect_tx.shared.b64 _, [%0], %1;"
                 :: "r"(addr), "r"(tx) : "memory");
}
__device__ __forceinline__ void mbar_wait_cluster(unsigned addr, unsigned parity) {
    unsigned done;
    asm volatile(
        "{\n\t.reg .pred p;\n\t"
        "mbarrier.try_wait.parity.acquire.cluster.shared::cta.b64 p, [%1], %2, 0x989680;\n\t"
        "selp.b32 %0, 1, 0, p;\n\t}"
        : "=r"(done) : "r"(addr), "r"(parity) : "memory");
    while (!done) {
        asm volatile(
            "{\n\t.reg .pred p;\n\t"
            "mbarrier.try_wait.parity.acquire.cluster.shared::cta.b64 p, [%1], %2, 0x989680;\n\t"
            "selp.b32 %0, 1, 0, p;\n\t}"
            : "=r"(done) : "r"(addr), "r"(parity) : "memory");
    }
}
// bulk SMEM->DSMEM copy: dst slice + mbarrier both in rank rk's CTA
__device__ __forceinline__ void bulk_dsmem(unsigned dst_local, unsigned src,
                                           unsigned mb_local, int rk) {
    unsigned d, m;
    asm volatile("mapa.shared::cluster.u32 %0, %1, %2;" : "=r"(d) : "r"(dst_local), "r"(rk));
    asm volatile("mapa.shared::cluster.u32 %0, %1, %2;" : "=r"(m) : "r"(mb_local), "r"(rk));
    asm volatile(
        "cp.async.bulk.shared::cluster.shared::cta.mbarrier::complete_tx::bytes "
        "[%0], [%1], %2, [%3];"
        :: "r"(d), "r"(src), "r"(128u), "r"(m) : "memory");
}
__device__ __forceinline__ float fsig(float x) {
    return __fdividef(1.f, 1.f + __expf(-x));
}
__device__ __forceinline__ float ftanh_(float x) {
    float e = __expf(2.f * x);
    return 1.f - __fdividef(2.f, e + 1.f);
}

// ---------------- K2: cluster-of-8 LSTM (PDL primary) ----------------
// h exchange per step: producers -> local h_stage, one bulk copy per rank
// (8 x 128B, 8 mbarrier tx-updates per dest instead of 256 scalar st.async).
__global__ void __cluster_dims__(8, 1, 1) __launch_bounds__(256, 1)
k2_lstm(const float* __restrict__ Wih, const float* __restrict__ Whh,
        const float* __restrict__ bih, const float* __restrict__ bhh) {
    asm volatile("griddepcontrol.launch_dependents;");

    __shared__ __align__(16) float h_buf[2][256];
    __shared__ __align__(16) float h_stage[2][32];
    __shared__ unsigned long long mbar_s[2];

    int tid = threadIdx.x;
    int rank = blockIdx.x;
    int jbase = rank * 32;
    int sk = tid & 7;
    int g = tid >> 3;

    unsigned mb0 = smem_u32(&mbar_s[0]);
    unsigned mb1 = smem_u32(&mbar_s[1]);

    if (tid == 0) {
        mbar_init_(mb0, 1);
        mbar_init_(mb1, 1);
        mbar_arrive_expect(mb1, 1024);
        mbar_arrive_expect(mb0, 1024);
    }
    h_buf[0][tid] = g_feat[tid];

    float bi[4];
#pragma unroll
    for (int sec = 0; sec < 4; sec++)
        bi[sec] = bih[sec * 256 + jbase + g] + bhh[sec * 256 + jbase + g];

    ulonglong2 wr[4][8];
#pragma unroll
    for (int sec = 0; sec < 4; sec++) {
        const float* baseI = Wih + (sec * 256 + jbase + g) * 256 + sk * 32;
        const float* baseH = Whh + (sec * 256 + jbase + g) * 256 + sk * 32;
#pragma unroll
        for (int q = 0; q < 8; q++) {
            int qq = q ^ sk;
            ulonglong2 a = *(const ulonglong2*)(baseI + qq * 4);
            ulonglong2 b = *(const ulonglong2*)(baseH + qq * 4);
            ADD2(a.x, b.x);
            ADD2(a.y, b.y);
            wr[sec][q] = a;
        }
    }
    __syncthreads();
    cluster_sync_();

    float c = 0.f;
    int par0 = 0, par1 = 0;
    unsigned dst_slice[2] = { smem_u32(&h_buf[0][jbase]), smem_u32(&h_buf[1][jbase]) };
    unsigned stage_addr[2] = { smem_u32(&h_stage[0][0]), smem_u32(&h_stage[1][0]) };

    // ---- step 0: gates = W_ih @ feat ----
    {
        unsigned long long a[4][2];
#pragma unroll
        for (int sec = 0; sec < 4; sec++) { a[sec][0] = 0ull; a[sec][1] = 0ull; }
        const ulonglong2* hb = (const ulonglong2*)(&h_buf[0][sk * 32]);
#pragma unroll
        for (int q = 0; q < 8; q++) {
            int qq = q ^ sk;
            ulonglong2 hx = hb[qq];
#pragma unroll
            for (int sec = 0; sec < 4; sec++) {
                ulonglong2 wv = *(const ulonglong2*)
                    (Wih + (sec * 256 + jbase + g) * 256 + sk * 32 + qq * 4);
                FMA2(a[sec][0], wv.x, hx.x);
                FMA2(a[sec][1], wv.y, hx.y);
            }
        }
        float fs[4];
#pragma unroll
        for (int sec = 0; sec < 4; sec++) {
            float l0, h0, l1, h1;
            UNPACK64(l0, h0, a[sec][0]);
            UNPACK64(l1, h1, a[sec][1]);
            fs[sec] = (l0 + h0) + (l1 + h1);
        }
#pragma unroll
        for (int m = 1; m < 8; m <<= 1)
#pragma unroll
            for (int sec = 0; sec < 4; sec++)
                fs[sec] += __shfl_xor_sync(0xffffffffu, fs[sec], m);
        if (sk == 0) {
            float gi = fsig(fs[0] + bi[0]);
            float gf = fsig(fs[1] + bi[1]);
            float gg = ftanh_(fs[2] + bi[2]);
            float go = fsig(fs[3] + bi[3]);
            c = gf * c + gi * gg;
            float h = go * ftanh_(c);
            g_Ht[(jbase + g) * HT_STRIDE + 0] = h;
            h_stage[0][g] = h;
        }
        __syncthreads();
        if (tid == 0) {
            asm volatile("fence.proxy.async.shared::cta;" ::: "memory");
#pragma unroll
            for (int rk = 0; rk < 8; rk++)
                bulk_dsmem(dst_slice[1], stage_addr[0], mb1, rk);
        }
    }

    // ---- steps 1..100 ----
    for (int s = 1; s <= 100; s++) {
        int b = s & 1;
        unsigned mb = b ? mb1 : mb0;
        mbar_wait_cluster(mb, b ? par1 : par0);
        if (b) par1 ^= 1; else par0 ^= 1;
        if (tid == 0 && s <= 98) mbar_arrive_expect(mb, 1024);

        unsigned long long a[4][2];
#pragma unroll
        for (int sec = 0; sec < 4; sec++) { a[sec][0] = 0ull; a[sec][1] = 0ull; }
        const ulonglong2* hb = (const ulonglong2*)(&h_buf[b][sk * 32]);
#pragma unroll
        for (int q = 0; q < 8; q++) {
            ulonglong2 hx = hb[q ^ sk];
#pragma unroll
            for (int sec = 0; sec < 4; sec++) {
                FMA2(a[sec][0], wr[sec][q].x, hx.x);
                FMA2(a[sec][1], wr[sec][q].y, hx.y);
            }
        }
        float fs[4];
#pragma unroll
        for (int sec = 0; sec < 4; sec++) {
            float l0, h0, l1, h1;
            UNPACK64(l0, h0, a[sec][0]);
            UNPACK64(l1, h1, a[sec][1]);
            fs[sec] = (l0 + h0) + (l1 + h1);
        }
#pragma unroll
        for (int m = 1; m < 8; m <<= 1)
#pragma unroll
            for (int sec = 0; sec < 4; sec++)
                fs[sec] += __shfl_xor_sync(0xffffffffu, fs[sec], m);

        if (sk == 0) {
            float gi = fsig(fs[0] + bi[0]);
            float gf = fsig(fs[1] + bi[1]);
            float gg = ftanh_(fs[2] + bi[2]);
            float go = fsig(fs[3] + bi[3]);
            c = gf * c + gi * gg;
            float h = go * ftanh_(c);
            g_Ht[(jbase + g) * HT_STRIDE + s] = h;
            if (s < 100) h_stage[s & 1][g] = h;
        }
        if (s < 100) {
            __syncthreads();
            if (tid == 0) {
                asm volatile("fence.proxy.async.shared::cta;" ::: "memory");
                int nb = (s + 1) & 1;
                unsigned dm = nb ? mb1 : mb0;
#pragma unroll
                for (int rk = 0; rk < 8; rk++)
                    bulk_dsmem(dst_slice[nb], stage_addr[s & 1], dm, rk);
            }
        }
        if (s == 25 || s == 51 || s == 77) {
            __syncthreads();
            if (tid == 0) {
                __threadfence();
                atomicAdd(&g_flag[s / 26], 1);
            }
        }
    }
    __syncthreads();
    if (tid == 0) {
        __threadfence();
        atomicAdd(&g_flag[3], 1);
    }
}

// ---------------- K3: decode (PDL secondary) ----------------
__global__ void __launch_bounds__(256, 2)
k3_decode(const float* __restrict__ W_dec,
          const float* __restrict__ b_dec,
          float* __restrict__ out) {
    extern __shared__ __align__(16) float dsm[];
    float* Wb0 = dsm;
    float* Wb1 = dsm + 8192;
    unsigned long long* Hs = (unsigned long long*)(dsm + 16384);
    float* Hsf = dsm + 16384;

    int tid = threadIdx.x;
    int w = tid >> 5, lane = tid & 31;
    int vh = w & 1, kh = (w >> 1) & 1, rgrp = w >> 2;
    int vbase = blockIdx.x * 256;
    int yb = blockIdx.y;
    int rbase = yb * 26;
    int vg = vh * 32 + lane;
    int v0 = vbase + vg * 4;

    for (int i = tid; i < 8192; i += 256) Hsf[i] = 0.f;

#pragma unroll
    for (int b = 0; b < 2; b++) {
        int kc = 4 * b;
        float* W = b ? Wb1 : Wb0;
#pragma unroll
        for (int q = 0; q < 8; q++) {
            int F = tid + 256 * q;
            int vcol = F >> 3, kq = F & 7;
            int v = vbase + vcol; if (v >= VOCAB) v = VOCAB - 1;
            float4 x = *(const float4*)(W_dec + v * 256 + kc * 32 + kq * 4);
            int cs = vcol ^ (kq << 2);
            W[(kq * 4 + 0) * 256 + cs] = x.x;
            W[(kq * 4 + 1) * 256 + cs] = x.y;
            W[(kq * 4 + 2) * 256 + cs] = x.z;
            W[(kq * 4 + 3) * 256 + cs] = x.w;
        }
    }

    if (tid == 0) {
        while (atomicAdd(&g_flag[yb], 0) < NLSTM) __nanosleep(128);
    }
    __syncthreads();
    __threadfence();

    {
        int s = lane, kg = w;
        if (s < 26) {
            int rg2 = (s < 13) ? 0 : 1;
            int q = s - rg2 * 13;
            int row = rbase + s;
            bool ok = (row < ROWS_OUT);
#pragma unroll
            for (int t = 0; t < 32; t++) {
                int k = kg + 8 * t;
                float h = ok ? __ldcg(g_Ht + k * HT_STRIDE + row) : 0.f;
                Hsf[(k * 16 + rg2 * 8) * 2 + q] = h;
            }
        }
    }
    __syncthreads();

    unsigned long long acc[7][4];
#pragma unroll
    for (int p2 = 0; p2 < 7; p2++)
#pragma unroll
        for (int c2 = 0; c2 < 4; c2++) acc[p2][c2] = 0ull;

    const float* Wmy = kh ? Wb1 : Wb0;

    for (int i = 0; i < 4; i++) {
        int kc = i + 4 * kh;
#pragma unroll
        for (int kk = 0; kk < 32; kk++) {
            float4 wq = *(const float4*)(Wmy + kk * 256 + ((vg ^ (kk >> 2)) << 2));
            unsigned long long wd0, wd1, wd2, wd3;
            DUP2(wd0, wq.x); DUP2(wd1, wq.y); DUP2(wd2, wq.z); DUP2(wd3, wq.w);
            const unsigned long long* hp = Hs + (kc * 32 + kk) * 16 + rgrp * 8;
            ulonglong2 hA = *(const ulonglong2*)hp;
            ulonglong2 hB = *(const ulonglong2*)(hp + 2);
            ulonglong2 hC = *(const ulonglong2*)(hp + 4);
            unsigned long long hD = hp[6];
            FMA2(acc[0][0], hA.x, wd0); FMA2(acc[0][1], hA.x, wd1);
            FMA2(acc[0][2], hA.x, wd2); FMA2(acc[0][3], hA.x, wd3);
            FMA2(acc[1][0], hA.y, wd0); FMA2(acc[1][1], hA.y, wd1);
            FMA2(acc[1][2], hA.y, wd2); FMA2(acc[1][3], hA.y, wd3);
            FMA2(acc[2][0], hB.x, wd0); FMA2(acc[2][1], hB.x, wd1);
            FMA2(acc[2][2], hB.x, wd2); FMA2(acc[2][3], hB.x, wd3);
            FMA2(acc[3][0], hB.y, wd0); FMA2(acc[3][1], hB.y, wd1);
            FMA2(acc[3][2], hB.y, wd2); FMA2(acc[3][3], hB.y, wd3);
            FMA2(acc[4][0], hC.x, wd0); FMA2(acc[4][1], hC.x, wd1);
            FMA2(acc[4][2], hC.x, wd2); FMA2(acc[4][3], hC.x, wd3);
            FMA2(acc[5][0], hC.y, wd0); FMA2(acc[5][1], hC.y, wd1);
            FMA2(acc[5][2], hC.y, wd2); FMA2(acc[5][3], hC.y, wd3);
            FMA2(acc[6][0], hD, wd0);   FMA2(acc[6][1], hD, wd1);
            FMA2(acc[6][2], hD, wd2);   FMA2(acc[6][3], hD, wd3);
        }
        __syncthreads();
        if (i < 3) {
#pragma unroll
            for (int b = 0; b < 2; b++) {
                int kcn = (i + 1) + 4 * b;
                float* W = b ? Wb1 : Wb0;
#pragma unroll
                for (int q = 0; q < 8; q++) {
                    int F = tid + 256 * q;
                    int vcol = F >> 3, kq = F & 7;
                    int v = vbase + vcol; if (v >= VOCAB) v = VOCAB - 1;
                    float4 x = *(const float4*)(W_dec + v * 256 + kcn * 32 + kq * 4);
                    int cs = vcol ^ (kq << 2);
                    W[(kq * 4 + 0) * 256 + cs] = x.x;
                    W[(kq * 4 + 1) * 256 + cs] = x.y;
                    W[(kq * 4 + 2) * 256 + cs] = x.z;
                    W[(kq * 4 + 3) * 256 + cs] = x.w;
                }
            }
            __syncthreads();
        }
    }

    unsigned long long* red = (unsigned long long*)dsm;
    int slot = (rgrp * 2 + vh) * 32 + lane;
    __syncthreads();
    if (kh == 1) {
#pragma unroll
        for (int p2 = 0; p2 < 7; p2++)
#pragma unroll
            for (int c2 = 0; c2 < 4; c2++)
                red[(p2 * 4 + c2) * 128 + slot] = acc[p2][c2];
    }
    __syncthreads();
    if (kh == 0) {
#pragma unroll
        for (int p2 = 0; p2 < 7; p2++)
#pragma unroll
            for (int c2 = 0; c2 < 4; c2++)
                ADD2(acc[p2][c2], red[(p2 * 4 + c2) * 128 + slot]);

        if (v0 < VOCAB) {
            float4 bv = *(const float4*)(b_dec + v0);
#pragma unroll
            for (int p2 = 0; p2 < 7; p2++) {
                int r0 = rbase + rgrp * 13 + 2 * p2;
                float lo0, hi0, lo1, hi1, lo2, hi2, lo3, hi3;
                UNPACK64(lo0, hi0, acc[p2][0]);
                UNPACK64(lo1, hi1, acc[p2][1]);
                UNPACK64(lo2, hi2, acc[p2][2]);
                UNPACK64(lo3, hi3, acc[p2][3]);
                if (r0 < ROWS_OUT) {
                    float4 o;
                    o.x = fmaxf(lo0 + bv.x, 0.f);
                    o.y = fmaxf(lo1 + bv.y, 0.f);
                    o.z = fmaxf(lo2 + bv.z, 0.f);
                    o.w = fmaxf(lo3 + bv.w, 0.f);
                    *(float4*)(out + r0 * VOCAB + v0) = o;
                }
                if (p2 < 6 && r0 + 1 < ROWS_OUT) {
                    float4 o;
                    o.x = fmaxf(hi0 + bv.x, 0.f);
                    o.y = fmaxf(hi1 + bv.y, 0.f);
                    o.z = fmaxf(hi2 + bv.z, 0.f);
                    o.w = fmaxf(hi3 + bv.w, 0.f);
                    *(float4*)(out + (r0 + 1) * VOCAB + v0) = o;
                }
            }
        }
    }
}

// ---------------- launch ----------------
extern "C" void kernel_launch(void* const* d_in, const int* in_sizes, int n_in,
                              void* d_out, int out_size) {
    const float* board    = (const float*)d_in[0];
    const float* conv_w   = (const float*)d_in[1];
    const float* conv_b   = (const float*)d_in[2];
    const float* bn_gamma = (const float*)d_in[3];
    const float* bn_beta  = (const float*)d_in[4];
    const float* p        = (const float*)d_in[5];
    const float* W_lin    = (const float*)d_in[6];
    const float* b_lin    = (const float*)d_in[7];
    const float* W_ih     = (const float*)d_in[8];
    const float* b_ih     = (const float*)d_in[9];
    const float* W_hh     = (const float*)d_in[10];
    const float* b_hh     = (const float*)d_in[11];
    const float* W_dec    = (const float*)d_in[12];
    const float* b_dec    = (const float*)d_in[13];
    float* out = (float*)d_out;

    const int K1_SMEM = (384 + 32 * 361) * 4;
    const int K2_PAD_SMEM = 184320;
    const int K3_SMEM = 98304;
    cudaFuncSetAttribute(k1_prep, cudaFuncAttributeMaxDynamicSharedMemorySize, K1_SMEM);
    cudaFuncSetAttribute(k2_lstm, cudaFuncAttributeMaxDynamicSharedMemorySize, K2_PAD_SMEM);
    cudaFuncSetAttribute(k3_decode, cudaFuncAttributeMaxDynamicSharedMemorySize, K3_SMEM);

    k1_prep<<<9, 512, K1_SMEM>>>(board, conv_w, conv_b, bn_gamma, bn_beta, p, W_lin, b_lin);
    k2_lstm<<<8, 256, K2_PAD_SMEM>>>(W_ih, W_hh, b_ih, b_hh);

    cudaLaunchConfig_t cfg = {};
    cfg.gridDim = dim3(NXT, NY, 1);
    cfg.blockDim = dim3(256, 1, 1);
    cfg.dynamicSmemBytes = K3_SMEM;
    cfg.stream = 0;
    cudaLaunchAttribute at[1];
    at[0].id = cudaLaunchAttributeProgrammaticStreamSerialization;
    at[0].val.programmaticStreamSerializationAllowed = 1;
    cfg.attrs = at;
    cfg.numAttrs = 1;
    cudaLaunchKernelEx(&cfg, k3_decode, W_dec, b_dec, out);
}

// round 16
// speedup vs baseline: 1.1356x; 1.1356x over previous
#include <cuda_runtime.h>
#include <math.h>

#define EMB 256
#define VOCAB 50000
#define ROWS_OUT 101
#define BN_EPS 1e-5f
#define NLSTM 8
#define NY 4
#define NXT 196
#define HT_STRIDE 104

// ---------------- packed f32x2 helpers ----------------
#define FMA2(acc, a, b) \
    asm("fma.rn.f32x2 %0, %1, %2, %0;" : "+l"(acc) : "l"(a), "l"(b))
#define ADD2(acc, b) \
    asm("add.rn.f32x2 %0, %0, %1;" : "+l"(acc) : "l"(b))
#define UNPACK64(lo, hi, v) do { unsigned _ulo, _uhi; \
    asm("mov.b64 {%0, %1}, %2;" : "=r"(_ulo), "=r"(_uhi) : "l"(v)); \
    lo = __uint_as_float(_ulo); hi = __uint_as_float(_uhi); } while (0)
#define PACK64(d, lo, hi) do { unsigned _a = __float_as_uint(lo), _b = __float_as_uint(hi); \
    asm("mov.b64 %0, {%1, %2};" : "=l"(d) : "r"(_a), "r"(_b)); } while (0)
#define DUP2(d, f) do { unsigned _u = __float_as_uint(f); \
    asm("mov.b64 %0, {%1, %1};" : "=l"(d) : "r"(_u)); } while (0)

// ---------------- device scratch ----------------
__device__ float g_d1[384];               // conv output (361 used, rest 0)
__device__ float g_feat[EMB];
__device__ float g_Ht[EMB * HT_STRIDE];   // transposed H: [k][step]
__device__ int g_flag[NY];
__device__ int g_dflag;

// ---------------- K1: grid of 9 CTAs ----------------
__device__ __forceinline__ void block_sum2(float& a, float& b,
                                           float* redA, float* redB) {
#pragma unroll
    for (int o = 16; o; o >>= 1) {
        a += __shfl_xor_sync(0xffffffffu, a, o);
        b += __shfl_xor_sync(0xffffffffu, b, o);
    }
    __syncthreads();
    if ((threadIdx.x & 31) == 0) {
        redA[threadIdx.x >> 5] = a;
        redB[threadIdx.x >> 5] = b;
    }
    __syncthreads();
    float sa = 0.f, sb = 0.f;
#pragma unroll
    for (int i = 0; i < 16; i++) { sa += redA[i]; sb += redB[i]; }
    a = sa; b = sb;
}

__global__ void k1_prep(const float* __restrict__ board,
                        const float* __restrict__ conv_w,
                        const float* __restrict__ conv_b,
                        const float* __restrict__ bn_gamma,
                        const float* __restrict__ bn_beta,
                        const float* __restrict__ p,
                        const float* __restrict__ Wlin,
                        const float* __restrict__ b_lin) {
    extern __shared__ __align__(16) float k1sm[];
    __shared__ float A[441];
    __shared__ float B[441];
    __shared__ float d2s[361];
    __shared__ float redA[16];
    __shared__ float redB[16];

    int tid = threadIdx.x;
    int bid = blockIdx.x;

    if (bid == 0) {
        if (tid < NY) g_flag[tid] = 0;

        float w[9];
#pragma unroll
        for (int q = 0; q < 9; q++) w[q] = conv_w[q];
        float cbias = conv_b[0], gamma = bn_gamma[0], beta = bn_beta[0];

        if (tid < 441) { A[tid] = 0.f; B[tid] = 0.f; }
        __syncthreads();
        if (tid < 361) {
            int r = tid / 19, c = tid % 19;
            A[(r + 1) * 21 + (c + 1)] = board[tid];
        }
        __syncthreads();

        float* src = A;
        float* dst = B;
        const int types[8] = {0, 0, 1, 0, 1, 0, 1, 2};
        const int pidx[8]  = {0, 1, 2, 3, 4, 5, 6, 0};

        for (int st = 0; st < 8; st++) {
            float y = 0.f;
            int base = 0;
            if (tid < 361) {
                int r = tid / 19, c = tid % 19;
                base = (r + 1) * 21 + (c + 1);
#pragma unroll
                for (int ki = 0; ki < 3; ki++)
#pragma unroll
                    for (int kj = 0; kj < 3; kj++)
                        y += w[ki * 3 + kj] * src[base + (ki - 1) * 21 + (kj - 1)];
                y += cbias;
            }
            float s1 = (tid < 361) ? y : 0.f;
            float s2 = s1 * s1;
            block_sum2(s1, s2, redA, redB);
            float mu = s1 * (1.f / 361.f);
            float var = s2 * (1.f / 361.f) - mu * mu;
            float rstd = rsqrtf(var + BN_EPS);

            if (tid < 361) {
                float z = gamma * (y - mu) * rstd + beta;
                float v;
                int t = types[st];
                if (t == 0)      v = fmaxf(p[pidx[st]] * z, 0.f);
                else if (t == 1) v = fmaxf(p[pidx[st]] * z + d2s[tid], 0.f);
                else             v = fmaxf(z, 0.f);
                dst[base] = v;
                if (st == 0 || t == 1) d2s[tid] = v;
            }
            __syncthreads();
            float* tmp = src; src = dst; dst = tmp;
        }

        if (tid < 384) {
            float v = 0.f;
            if (tid < 361) {
                int r = tid / 19, c = tid % 19;
                v = src[(r + 1) * 21 + (c + 1)];
            }
            g_d1[tid] = v;
        }
        __syncthreads();
        if (tid == 0) {
            __threadfence();
            atomicExch(&g_dflag, 1);
        }
    } else {
        float* d1s = k1sm;            // 384
        float* ws  = k1sm + 384;      // 32 * 361

        int ebase = (bid - 1) * 32;
        for (int idx = tid; idx < 32 * 361; idx += 512)
            ws[idx] = Wlin[ebase * 361 + idx];

        if (tid == 0) {
            while (atomicAdd(&g_dflag, 0) == 0) __nanosleep(64);
        }
        __syncthreads();
        __threadfence();
        for (int i = tid; i < 384; i += 512) d1s[i] = g_d1[i];
        __syncthreads();

        int wi = tid >> 5, lane = tid & 31;
        const float* r0 = ws + (2 * wi) * 361;
        const float* r1 = ws + (2 * wi + 1) * 361;
        float a0 = 0.f, a1 = 0.f;
#pragma unroll
        for (int t = 0; t < 12; t++) {
            int j = lane + 32 * t;
            if (j < 361) {
                float d = d1s[j];
                a0 += r0[j] * d;
                a1 += r1[j] * d;
            }
        }
#pragma unroll
        for (int m = 16; m; m >>= 1) {
            a0 += __shfl_xor_sync(0xffffffffu, a0, m);
            a1 += __shfl_xor_sync(0xffffffffu, a1, m);
        }
        if (lane < 2) {
            int e = ebase + 2 * wi + lane;
            float v = (lane == 0) ? a0 : a1;
            g_feat[e] = v + b_lin[e];
        }
    }
}

// ---------------- cluster / mbarrier helpers ----------------
__device__ __forceinline__ void cluster_sync_() {
    asm volatile("barrier.cluster.arrive.aligned;" ::: "memory");
    asm volatile("barrier.cluster.wait.aligned;" ::: "memory");
}
__device__ __forceinline__ unsigned smem_u32(const void* p) {
    unsigned a;
    asm("{ .reg .u64 t; cvta.to.shared.u64 t, %1; cvt.u32.u64 %0, t; }"
        : "=r"(a) : "l"(p));
    return a;
}
__device__ __forceinline__ void mbar_init_(unsigned addr, unsigned cnt) {
    asm volatile("mbarrier.init.shared.b64 [%0], %1;" :: "r"(addr), "r"(cnt) : "memory");
}
__device__ __forceinline__ void mbar_arrive_expect(unsigned addr, unsigned tx) {
    asm volatile("mbarrier.arrive.expect_tx.shared.b64 _, [%0], %1;"
                 :: "r"(addr), "r"(tx) : "memory");
}
__device__ __forceinline__ void mbar_wait_cluster(unsigned addr, unsigned parity) {
    unsigned done;
    asm volatile(
        "{\n\t.reg .pred p;\n\t"
        "mbarrier.try_wait.parity.acquire.cluster.shared::cta.b64 p, [%1], %2, 0x989680;\n\t"
        "selp.b32 %0, 1, 0, p;\n\t}"
        : "=r"(done) : "r"(addr), "r"(parity) : "memory");
    while (!done) {
        asm volatile(
            "{\n\t.reg .pred p;\n\t"
            "mbarrier.try_wait.parity.acquire.cluster.shared::cta.b64 p, [%1], %2, 0x989680;\n\t"
            "selp.b32 %0, 1, 0, p;\n\t}"
            : "=r"(done) : "r"(addr), "r"(parity) : "memory");
    }
}
// packed b64 st.async: delivers (h_g, h_{g+1}) in one 8-byte transaction
__device__ __forceinline__ void st_async_remote64(unsigned daddr, unsigned dmbar,
                                                  int rk, unsigned long long v) {
    unsigned ra, rm;
    asm volatile("mapa.shared::cluster.u32 %0, %1, %2;" : "=r"(ra) : "r"(daddr), "r"(rk));
    asm volatile("mapa.shared::cluster.u32 %0, %1, %2;" : "=r"(rm) : "r"(dmbar), "r"(rk));
    asm volatile("st.async.shared::cluster.mbarrier::complete_tx::bytes.b64 [%0], %1, [%2];"
                 :: "r"(ra), "l"(v), "r"(rm) : "memory");
}
__device__ __forceinline__ float fsig(float x) {
    return __fdividef(1.f, 1.f + __expf(-x));
}
__device__ __forceinline__ float ftanh_(float x) {
    float e = __expf(2.f * x);
    return 1.f - __fdividef(2.f, e + 1.f);
}

// ---------------- K2: cluster-of-8 LSTM (PDL primary) ----------------
// h exchange: pair-packed .b64 st.async -> 128 stores/step (was 256 scalar).
__global__ void __cluster_dims__(8, 1, 1) __launch_bounds__(256, 1)
k2_lstm(const float* __restrict__ Wih, const float* __restrict__ Whh,
        const float* __restrict__ bih, const float* __restrict__ bhh) {
    asm volatile("griddepcontrol.launch_dependents;");

    __shared__ __align__(16) float h_buf[2][256];
    __shared__ unsigned long long mbar_s[2];

    int tid = threadIdx.x;
    int rank = blockIdx.x;
    int jbase = rank * 32;
    int sk = tid & 7;
    int g = tid >> 3;

    unsigned mb0 = smem_u32(&mbar_s[0]);
    unsigned mb1 = smem_u32(&mbar_s[1]);

    if (tid == 0) {
        mbar_init_(mb0, 1);
        mbar_init_(mb1, 1);
        mbar_arrive_expect(mb1, 1024);
        mbar_arrive_expect(mb0, 1024);
    }
    h_buf[0][tid] = g_feat[tid];

    float bi[4];
#pragma unroll
    for (int sec = 0; sec < 4; sec++)
        bi[sec] = bih[sec * 256 + jbase + g] + bhh[sec * 256 + jbase + g];

    ulonglong2 wr[4][8];
#pragma unroll
    for (int sec = 0; sec < 4; sec++) {
        const float* baseI = Wih + (sec * 256 + jbase + g) * 256 + sk * 32;
        const float* baseH = Whh + (sec * 256 + jbase + g) * 256 + sk * 32;
#pragma unroll
        for (int q = 0; q < 8; q++) {
            int qq = q ^ sk;
            ulonglong2 a = *(const ulonglong2*)(baseI + qq * 4);
            ulonglong2 b = *(const ulonglong2*)(baseH + qq * 4);
            ADD2(a.x, b.x);
            ADD2(a.y, b.y);
            wr[sec][q] = a;
        }
    }
    __syncthreads();
    cluster_sync_();

    float c = 0.f;
    int par0 = 0, par1 = 0;

    // ---- step 0: gates = W_ih @ feat ----
    {
        unsigned long long a[4][2];
#pragma unroll
        for (int sec = 0; sec < 4; sec++) { a[sec][0] = 0ull; a[sec][1] = 0ull; }
        const ulonglong2* hb = (const ulonglong2*)(&h_buf[0][sk * 32]);
#pragma unroll
        for (int q = 0; q < 8; q++) {
            int qq = q ^ sk;
            ulonglong2 hx = hb[qq];
#pragma unroll
            for (int sec = 0; sec < 4; sec++) {
                ulonglong2 wv = *(const ulonglong2*)
                    (Wih + (sec * 256 + jbase + g) * 256 + sk * 32 + qq * 4);
                FMA2(a[sec][0], wv.x, hx.x);
                FMA2(a[sec][1], wv.y, hx.y);
            }
        }
        float fs[4];
#pragma unroll
        for (int sec = 0; sec < 4; sec++) {
            float l0, h0, l1, h1;
            UNPACK64(l0, h0, a[sec][0]);
            UNPACK64(l1, h1, a[sec][1]);
            fs[sec] = (l0 + h0) + (l1 + h1);
        }
#pragma unroll
        for (int m = 1; m < 8; m <<= 1)
#pragma unroll
            for (int sec = 0; sec < 4; sec++)
                fs[sec] += __shfl_xor_sync(0xffffffffu, fs[sec], m);
        float hval = 0.f;
        if (sk == 0) {
            float gi = fsig(fs[0] + bi[0]);
            float gf = fsig(fs[1] + bi[1]);
            float gg = ftanh_(fs[2] + bi[2]);
            float go = fsig(fs[3] + bi[3]);
            c = gf * c + gi * gg;
            hval = go * ftanh_(c);
            g_Ht[(jbase + g) * HT_STRIDE + 0] = hval;
        }
        float hhi = __shfl_down_sync(0xffffffffu, hval, 8);
        if ((tid & 15) == 0) {   // sk==0 && g even
            unsigned long long pk;
            PACK64(pk, hval, hhi);
            unsigned da = smem_u32(&h_buf[1][jbase + g]);
#pragma unroll
            for (int rk = 0; rk < 8; rk++) st_async_remote64(da, mb1, rk, pk);
        }
    }

    // ---- steps 1..100 ----
    for (int s = 1; s <= 100; s++) {
        int b = s & 1;
        unsigned mb = b ? mb1 : mb0;
        mbar_wait_cluster(mb, b ? par1 : par0);
        if (b) par1 ^= 1; else par0 ^= 1;
        if (tid == 0 && s <= 98) mbar_arrive_expect(mb, 1024);

        unsigned long long a[4][2];
#pragma unroll
        for (int sec = 0; sec < 4; sec++) { a[sec][0] = 0ull; a[sec][1] = 0ull; }
        const ulonglong2* hb = (const ulonglong2*)(&h_buf[b][sk * 32]);
#pragma unroll
        for (int q = 0; q < 8; q++) {
            ulonglong2 hx = hb[q ^ sk];
#pragma unroll
            for (int sec = 0; sec < 4; sec++) {
                FMA2(a[sec][0], wr[sec][q].x, hx.x);
                FMA2(a[sec][1], wr[sec][q].y, hx.y);
            }
        }
        float fs[4];
#pragma unroll
        for (int sec = 0; sec < 4; sec++) {
            float l0, h0, l1, h1;
            UNPACK64(l0, h0, a[sec][0]);
            UNPACK64(l1, h1, a[sec][1]);
            fs[sec] = (l0 + h0) + (l1 + h1);
        }
#pragma unroll
        for (int m = 1; m < 8; m <<= 1)
#pragma unroll
            for (int sec = 0; sec < 4; sec++)
                fs[sec] += __shfl_xor_sync(0xffffffffu, fs[sec], m);

        float hval = 0.f;
        if (sk == 0) {
            float gi = fsig(fs[0] + bi[0]);
            float gf = fsig(fs[1] + bi[1]);
            float gg = ftanh_(fs[2] + bi[2]);
            float go = fsig(fs[3] + bi[3]);
            c = gf * c + gi * gg;
            hval = go * ftanh_(c);
            g_Ht[(jbase + g) * HT_STRIDE + s] = hval;
        }
        if (s < 100) {
            float hhi = __shfl_down_sync(0xffffffffu, hval, 8);
            if ((tid & 15) == 0) {   // sk==0 && g even
                unsigned long long pk;
                PACK64(pk, hval, hhi);
                int nb = (s + 1) & 1;
                unsigned da = smem_u32(&h_buf[nb][jbase + g]);
                unsigned dm = nb ? mb1 : mb0;
#pragma unroll
                for (int rk = 0; rk < 8; rk++) st_async_remote64(da, dm, rk, pk);
            }
        }
        if (s == 25 || s == 51 || s == 77) {
            __syncthreads();
            if (tid == 0) {
                __threadfence();
                atomicAdd(&g_flag[s / 26], 1);
            }
        }
    }
    __syncthreads();
    if (tid == 0) {
        __threadfence();
        atomicAdd(&g_flag[3], 1);
    }
}

// ---------------- K3: decode (PDL secondary) ----------------
__global__ void __launch_bounds__(256, 2)
k3_decode(const float* __restrict__ W_dec,
          const float* __restrict__ b_dec,
          float* __restrict__ out) {
    extern __shared__ __align__(16) float dsm[];
    float* Wb0 = dsm;
    float* Wb1 = dsm + 8192;
    unsigned long long* Hs = (unsigned long long*)(dsm + 16384);
    float* Hsf = dsm + 16384;

    int tid = threadIdx.x;
    int w = tid >> 5, lane = tid & 31;
    int vh = w & 1, kh = (w >> 1) & 1, rgrp = w >> 2;
    int vbase = blockIdx.x * 256;
    int yb = blockIdx.y;
    int rbase = yb * 26;
    int vg = vh * 32 + lane;
    int v0 = vbase + vg * 4;

    for (int i = tid; i < 8192; i += 256) Hsf[i] = 0.f;

#pragma unroll
    for (int b = 0; b < 2; b++) {
        int kc = 4 * b;
        float* W = b ? Wb1 : Wb0;
#pragma unroll
        for (int q = 0; q < 8; q++) {
            int F = tid + 256 * q;
            int vcol = F >> 3, kq = F & 7;
            int v = vbase + vcol; if (v >= VOCAB) v = VOCAB - 1;
            float4 x = *(const float4*)(W_dec + v * 256 + kc * 32 + kq * 4);
            int cs = vcol ^ (kq << 2);
            W[(kq * 4 + 0) * 256 + cs] = x.x;
            W[(kq * 4 + 1) * 256 + cs] = x.y;
            W[(kq * 4 + 2) * 256 + cs] = x.z;
            W[(kq * 4 + 3) * 256 + cs] = x.w;
        }
    }

    if (tid == 0) {
        while (atomicAdd(&g_flag[yb], 0) < NLSTM) __nanosleep(128);
    }
    __syncthreads();
    __threadfence();

    {
        int s = lane, kg = w;
        if (s < 26) {
            int rg2 = (s < 13) ? 0 : 1;
            int q = s - rg2 * 13;
            int row = rbase + s;
            bool ok = (row < ROWS_OUT);
#pragma unroll
            for (int t = 0; t < 32; t++) {
                int k = kg + 8 * t;
                float h = ok ? __ldcg(g_Ht + k * HT_STRIDE + row) : 0.f;
                Hsf[(k * 16 + rg2 * 8) * 2 + q] = h;
            }
        }
    }
    __syncthreads();

    unsigned long long acc[7][4];
#pragma unroll
    for (int p2 = 0; p2 < 7; p2++)
#pragma unroll
        for (int c2 = 0; c2 < 4; c2++) acc[p2][c2] = 0ull;

    const float* Wmy = kh ? Wb1 : Wb0;

    for (int i = 0; i < 4; i++) {
        int kc = i + 4 * kh;
#pragma unroll
        for (int kk = 0; kk < 32; kk++) {
            float4 wq = *(const float4*)(Wmy + kk * 256 + ((vg ^ (kk >> 2)) << 2));
            unsigned long long wd0, wd1, wd2, wd3;
            DUP2(wd0, wq.x); DUP2(wd1, wq.y); DUP2(wd2, wq.z); DUP2(wd3, wq.w);
            const unsigned long long* hp = Hs + (kc * 32 + kk) * 16 + rgrp * 8;
            ulonglong2 hA = *(const ulonglong2*)hp;
            ulonglong2 hB = *(const ulonglong2*)(hp + 2);
            ulonglong2 hC = *(const ulonglong2*)(hp + 4);
            unsigned long long hD = hp[6];
            FMA2(acc[0][0], hA.x, wd0); FMA2(acc[0][1], hA.x, wd1);
            FMA2(acc[0][2], hA.x, wd2); FMA2(acc[0][3], hA.x, wd3);
            FMA2(acc[1][0], hA.y, wd0); FMA2(acc[1][1], hA.y, wd1);
            FMA2(acc[1][2], hA.y, wd2); FMA2(acc[1][3], hA.y, wd3);
            FMA2(acc[2][0], hB.x, wd0); FMA2(acc[2][1], hB.x, wd1);
            FMA2(acc[2][2], hB.x, wd2); FMA2(acc[2][3], hB.x, wd3);
            FMA2(acc[3][0], hB.y, wd0); FMA2(acc[3][1], hB.y, wd1);
            FMA2(acc[3][2], hB.y, wd2); FMA2(acc[3][3], hB.y, wd3);
            FMA2(acc[4][0], hC.x, wd0); FMA2(acc[4][1], hC.x, wd1);
            FMA2(acc[4][2], hC.x, wd2); FMA2(acc[4][3], hC.x, wd3);
            FMA2(acc[5][0], hC.y, wd0); FMA2(acc[5][1], hC.y, wd1);
            FMA2(acc[5][2], hC.y, wd2); FMA2(acc[5][3], hC.y, wd3);
            FMA2(acc[6][0], hD, wd0);   FMA2(acc[6][1], hD, wd1);
            FMA2(acc[6][2], hD, wd2);   FMA2(acc[6][3], hD, wd3);
        }
        __syncthreads();
        if (i < 3) {
#pragma unroll
            for (int b = 0; b < 2; b++) {
                int kcn = (i + 1) + 4 * b;
                float* W = b ? Wb1 : Wb0;
#pragma unroll
                for (int q = 0; q < 8; q++) {
                    int F = tid + 256 * q;
                    int vcol = F >> 3, kq = F & 7;
                    int v = vbase + vcol; if (v >= VOCAB) v = VOCAB - 1;
                    float4 x = *(const float4*)(W_dec + v * 256 + kcn * 32 + kq * 4);
                    int cs = vcol ^ (kq << 2);
                    W[(kq * 4 + 0) * 256 + cs] = x.x;
                    W[(kq * 4 + 1) * 256 + cs] = x.y;
                    W[(kq * 4 + 2) * 256 + cs] = x.z;
                    W[(kq * 4 + 3) * 256 + cs] = x.w;
                }
            }
            __syncthreads();
        }
    }

    unsigned long long* red = (unsigned long long*)dsm;
    int slot = (rgrp * 2 + vh) * 32 + lane;
    __syncthreads();
    if (kh == 1) {
#pragma unroll
        for (int p2 = 0; p2 < 7; p2++)
#pragma unroll
            for (int c2 = 0; c2 < 4; c2++)
                red[(p2 * 4 + c2) * 128 + slot] = acc[p2][c2];
    }
    __syncthreads();
    if (kh == 0) {
#pragma unroll
        for (int p2 = 0; p2 < 7; p2++)
#pragma unroll
            for (int c2 = 0; c2 < 4; c2++)
                ADD2(acc[p2][c2], red[(p2 * 4 + c2) * 128 + slot]);

        if (v0 < VOCAB) {
            float4 bv = *(const float4*)(b_dec + v0);
#pragma unroll
            for (int p2 = 0; p2 < 7; p2++) {
                int r0 = rbase + rgrp * 13 + 2 * p2;
                float lo0, hi0, lo1, hi1, lo2, hi2, lo3, hi3;
                UNPACK64(lo0, hi0, acc[p2][0]);
                UNPACK64(lo1, hi1, acc[p2][1]);
                UNPACK64(lo2, hi2, acc[p2][2]);
                UNPACK64(lo3, hi3, acc[p2][3]);
                if (r0 < ROWS_OUT) {
                    float4 o;
                    o.x = fmaxf(lo0 + bv.x, 0.f);
                    o.y = fmaxf(lo1 + bv.y, 0.f);
                    o.z = fmaxf(lo2 + bv.z, 0.f);
                    o.w = fmaxf(lo3 + bv.w, 0.f);
                    *(float4*)(out + r0 * VOCAB + v0) = o;
                }
                if (p2 < 6 && r0 + 1 < ROWS_OUT) {
                    float4 o;
                    o.x = fmaxf(hi0 + bv.x, 0.f);
                    o.y = fmaxf(hi1 + bv.y, 0.f);
                    o.z = fmaxf(hi2 + bv.z, 0.f);
                    o.w = fmaxf(hi3 + bv.w, 0.f);
                    *(float4*)(out + (r0 + 1) * VOCAB + v0) = o;
                }
            }
        }
    }
}

// ---------------- launch ----------------
extern "C" void kernel_launch(void* const* d_in, const int* in_sizes, int n_in,
                              void* d_out, int out_size) {
    const float* board    = (const float*)d_in[0];
    const float* conv_w   = (const float*)d_in[1];
    const float* conv_b   = (const float*)d_in[2];
    const float* bn_gamma = (const float*)d_in[3];
    const float* bn_beta  = (const float*)d_in[4];
    const float* p        = (const float*)d_in[5];
    const float* W_lin    = (const float*)d_in[6];
    const float* b_lin    = (const float*)d_in[7];
    const float* W_ih     = (const float*)d_in[8];
    const float* b_ih     = (const float*)d_in[9];
    const float* W_hh     = (const float*)d_in[10];
    const float* b_hh     = (const float*)d_in[11];
    const float* W_dec    = (const float*)d_in[12];
    const float* b_dec    = (const float*)d_in[13];
    float* out = (float*)d_out;

    const int K1_SMEM = (384 + 32 * 361) * 4;
    const int K2_PAD_SMEM = 184320;
    const int K3_SMEM = 98304;
    cudaFuncSetAttribute(k1_prep, cudaFuncAttributeMaxDynamicSharedMemorySize, K1_SMEM);
    cudaFuncSetAttribute(k2_lstm, cudaFuncAttributeMaxDynamicSharedMemorySize, K2_PAD_SMEM);
    cudaFuncSetAttribute(k3_decode, cudaFuncAttributeMaxDynamicSharedMemorySize, K3_SMEM);

    k1_prep<<<9, 512, K1_SMEM>>>(board, conv_w, conv_b, bn_gamma, bn_beta, p, W_lin, b_lin);
    k2_lstm<<<8, 256, K2_PAD_SMEM>>>(W_ih, W_hh, b_ih, b_hh);

    cudaLaunchConfig_t cfg = {};
    cfg.gridDim = dim3(NXT, NY, 1);
    cfg.blockDim = dim3(256, 1, 1);
    cfg.dynamicSmemBytes = K3_SMEM;
    cfg.stream = 0;
    cudaLaunchAttribute at[1];
    at[0].id = cudaLaunchAttributeProgrammaticStreamSerialization;
    at[0].val.programmaticStreamSerializationAllowed = 1;
    cfg.attrs = at;
    cfg.numAttrs = 1;
    cudaLaunchKernelEx(&cfg, k3_decode, W_dec, b_dec, out);
}

// round 17
// speedup vs baseline: 1.2077x; 1.0635x over previous
#include <cuda_runtime.h>
#include <math.h>

#define EMB 256
#define VOCAB 50000
#define ROWS_OUT 101
#define BN_EPS 1e-5f
#define NLSTM 8
#define NY 4
#define NXT 196
#define HT_STRIDE 104

// ---------------- packed f32x2 helpers ----------------
#define FMA2(acc, a, b) \
    asm("fma.rn.f32x2 %0, %1, %2, %0;" : "+l"(acc) : "l"(a), "l"(b))
#define ADD2(acc, b) \
    asm("add.rn.f32x2 %0, %0, %1;" : "+l"(acc) : "l"(b))
#define UNPACK64(lo, hi, v) do { unsigned _ulo, _uhi; \
    asm("mov.b64 {%0, %1}, %2;" : "=r"(_ulo), "=r"(_uhi) : "l"(v)); \
    lo = __uint_as_float(_ulo); hi = __uint_as_float(_uhi); } while (0)
#define PACK64(d, lo, hi) do { unsigned _a = __float_as_uint(lo), _b = __float_as_uint(hi); \
    asm("mov.b64 %0, {%1, %2};" : "=l"(d) : "r"(_a), "r"(_b)); } while (0)
#define DUP2(d, f) do { unsigned _u = __float_as_uint(f); \
    asm("mov.b64 %0, {%1, %1};" : "=l"(d) : "r"(_u)); } while (0)

// ---------------- device scratch ----------------
__device__ float g_d1[384];
__device__ float g_feat[EMB];
__device__ float g_Ht[EMB * HT_STRIDE];
__device__ int g_flag[NY];
__device__ int g_dflag;
__device__ int g_featflag;    // bitmask of finished feat CTAs (never reset; stale-pass benign)

// ---------------- K1: grid of 9 CTAs (PDL primary of K2) ----------------
__device__ __forceinline__ void block_sum2(float& a, float& b,
                                           float* redA, float* redB) {
#pragma unroll
    for (int o = 16; o; o >>= 1) {
        a += __shfl_xor_sync(0xffffffffu, a, o);
        b += __shfl_xor_sync(0xffffffffu, b, o);
    }
    __syncthreads();
    if ((threadIdx.x & 31) == 0) {
        redA[threadIdx.x >> 5] = a;
        redB[threadIdx.x >> 5] = b;
    }
    __syncthreads();
    float sa = 0.f, sb = 0.f;
#pragma unroll
    for (int i = 0; i < 16; i++) { sa += redA[i]; sb += redB[i]; }
    a = sa; b = sb;
}

__global__ void k1_prep(const float* __restrict__ board,
                        const float* __restrict__ conv_w,
                        const float* __restrict__ conv_b,
                        const float* __restrict__ bn_gamma,
                        const float* __restrict__ bn_beta,
                        const float* __restrict__ p,
                        const float* __restrict__ Wlin,
                        const float* __restrict__ b_lin) {
    // release K2 immediately: its weight load overlaps our conv/feat
    asm volatile("griddepcontrol.launch_dependents;");

    extern __shared__ __align__(16) float k1sm[];
    __shared__ float A[441];
    __shared__ float B[441];
    __shared__ float d2s[361];
    __shared__ float redA[16];
    __shared__ float redB[16];

    int tid = threadIdx.x;
    int bid = blockIdx.x;

    if (bid == 0) {
        if (tid < NY) g_flag[tid] = 0;

        float w[9];
#pragma unroll
        for (int q = 0; q < 9; q++) w[q] = conv_w[q];
        float cbias = conv_b[0], gamma = bn_gamma[0], beta = bn_beta[0];

        if (tid < 441) { A[tid] = 0.f; B[tid] = 0.f; }
        __syncthreads();
        if (tid < 361) {
            int r = tid / 19, c = tid % 19;
            A[(r + 1) * 21 + (c + 1)] = board[tid];
        }
        __syncthreads();

        float* src = A;
        float* dst = B;
        const int types[8] = {0, 0, 1, 0, 1, 0, 1, 2};
        const int pidx[8]  = {0, 1, 2, 3, 4, 5, 6, 0};

        for (int st = 0; st < 8; st++) {
            float y = 0.f;
            int base = 0;
            if (tid < 361) {
                int r = tid / 19, c = tid % 19;
                base = (r + 1) * 21 + (c + 1);
#pragma unroll
                for (int ki = 0; ki < 3; ki++)
#pragma unroll
                    for (int kj = 0; kj < 3; kj++)
                        y += w[ki * 3 + kj] * src[base + (ki - 1) * 21 + (kj - 1)];
                y += cbias;
            }
            float s1 = (tid < 361) ? y : 0.f;
            float s2 = s1 * s1;
            block_sum2(s1, s2, redA, redB);
            float mu = s1 * (1.f / 361.f);
            float var = s2 * (1.f / 361.f) - mu * mu;
            float rstd = rsqrtf(var + BN_EPS);

            if (tid < 361) {
                float z = gamma * (y - mu) * rstd + beta;
                float v;
                int t = types[st];
                if (t == 0)      v = fmaxf(p[pidx[st]] * z, 0.f);
                else if (t == 1) v = fmaxf(p[pidx[st]] * z + d2s[tid], 0.f);
                else             v = fmaxf(z, 0.f);
                dst[base] = v;
                if (st == 0 || t == 1) d2s[tid] = v;
            }
            __syncthreads();
            float* tmp = src; src = dst; dst = tmp;
        }

        if (tid < 384) {
            float v = 0.f;
            if (tid < 361) {
                int r = tid / 19, c = tid % 19;
                v = src[(r + 1) * 21 + (c + 1)];
            }
            g_d1[tid] = v;
        }
        __syncthreads();
        if (tid == 0) {
            __threadfence();
            atomicExch(&g_dflag, 1);
        }
    } else {
        float* d1s = k1sm;            // 384
        float* ws  = k1sm + 384;      // 32 * 361

        int ebase = (bid - 1) * 32;
        for (int idx = tid; idx < 32 * 361; idx += 512)
            ws[idx] = Wlin[ebase * 361 + idx];

        if (tid == 0) {
            while (atomicAdd(&g_dflag, 0) == 0) __nanosleep(64);
        }
        __syncthreads();
        __threadfence();
        for (int i = tid; i < 384; i += 512) d1s[i] = g_d1[i];
        __syncthreads();

        int wi = tid >> 5, lane = tid & 31;
        const float* r0 = ws + (2 * wi) * 361;
        const float* r1 = ws + (2 * wi + 1) * 361;
        float a0 = 0.f, a1 = 0.f;
#pragma unroll
        for (int t = 0; t < 12; t++) {
            int j = lane + 32 * t;
            if (j < 361) {
                float d = d1s[j];
                a0 += r0[j] * d;
                a1 += r1[j] * d;
            }
        }
#pragma unroll
        for (int m = 16; m; m >>= 1) {
            a0 += __shfl_xor_sync(0xffffffffu, a0, m);
            a1 += __shfl_xor_sync(0xffffffffu, a1, m);
        }
        if (lane < 2) {
            int e = ebase + 2 * wi + lane;
            float v = (lane == 0) ? a0 : a1;
            g_feat[e] = v + b_lin[e];
        }
        __syncthreads();
        if (tid == 0) {
            __threadfence();
            atomicOr(&g_featflag, 1 << (bid - 1));
        }
    }
}

// ---------------- cluster / mbarrier helpers ----------------
__device__ __forceinline__ void cluster_sync_() {
    asm volatile("barrier.cluster.arrive.aligned;" ::: "memory");
    asm volatile("barrier.cluster.wait.aligned;" ::: "memory");
}
__device__ __forceinline__ unsigned smem_u32(const void* p) {
    unsigned a;
    asm("{ .reg .u64 t; cvta.to.shared.u64 t, %1; cvt.u32.u64 %0, t; }"
        : "=r"(a) : "l"(p));
    return a;
}
__device__ __forceinline__ void mbar_init_(unsigned addr, unsigned cnt) {
    asm volatile("mbarrier.init.shared.b64 [%0], %1;" :: "r"(addr), "r"(cnt) : "memory");
}
__device__ __forceinline__ void mbar_arrive_expect(unsigned addr, unsigned tx) {
    asm volatile("mbarrier.arrive.expect_tx.shared.b64 _, [%0], %1;"
                 :: "r"(addr), "r"(tx) : "memory");
}
__device__ __forceinline__ void mbar_wait_cluster(unsigned addr, unsigned parity) {
    unsigned done;
    asm volatile(
        "{\n\t.reg .pred p;\n\t"
        "mbarrier.try_wait.parity.acquire.cluster.shared::cta.b64 p, [%1], %2, 0x989680;\n\t"
        "selp.b32 %0, 1, 0, p;\n\t}"
        : "=r"(done) : "r"(addr), "r"(parity) : "memory");
    while (!done) {
        asm volatile(
            "{\n\t.reg .pred p;\n\t"
            "mbarrier.try_wait.parity.acquire.cluster.shared::cta.b64 p, [%1], %2, 0x989680;\n\t"
            "selp.b32 %0, 1, 0, p;\n\t}"
            : "=r"(done) : "r"(addr), "r"(parity) : "memory");
    }
}
__device__ __forceinline__ void st_async_remote64(unsigned daddr, unsigned dmbar,
                                                  int rk, unsigned long long v) {
    unsigned ra, rm;
    asm volatile("mapa.shared::cluster.u32 %0, %1, %2;" : "=r"(ra) : "r"(daddr), "r"(rk));
    asm volatile("mapa.shared::cluster.u32 %0, %1, %2;" : "=r"(rm) : "r"(dmbar), "r"(rk));
    asm volatile("st.async.shared::cluster.mbarrier::complete_tx::bytes.b64 [%0], %1, [%2];"
                 :: "r"(ra), "l"(v), "r"(rm) : "memory");
}
__device__ __forceinline__ float fsig(float x) {
    return __fdividef(1.f, 1.f + __expf(-x));
}
__device__ __forceinline__ float ftanh_(float x) {
    float e = __expf(2.f * x);
    return 1.f - __fdividef(2.f, e + 1.f);
}

// ---------------- K2: cluster-of-8 LSTM (PDL secondary of K1, primary of K3) ----------------
__global__ void __cluster_dims__(8, 1, 1) __launch_bounds__(256, 1)
k2_lstm(const float* __restrict__ Wih, const float* __restrict__ Whh,
        const float* __restrict__ bih, const float* __restrict__ bhh) {
    asm volatile("griddepcontrol.launch_dependents;");

    __shared__ __align__(16) float h_buf[2][256];
    __shared__ unsigned long long mbar_s[2];

    int tid = threadIdx.x;
    int rank = blockIdx.x;
    int jbase = rank * 32;
    int sk = tid & 7;
    int g = tid >> 3;

    unsigned mb0 = smem_u32(&mbar_s[0]);
    unsigned mb1 = smem_u32(&mbar_s[1]);

    if (tid == 0) {
        mbar_init_(mb0, 1);
        mbar_init_(mb1, 1);
        mbar_arrive_expect(mb1, 1024);
        mbar_arrive_expect(mb0, 1024);
    }

    float bi[4];
#pragma unroll
    for (int sec = 0; sec < 4; sec++)
        bi[sec] = bih[sec * 256 + jbase + g] + bhh[sec * 256 + jbase + g];

    // weight load overlaps k1 (PDL)
    ulonglong2 wr[4][8];
#pragma unroll
    for (int sec = 0; sec < 4; sec++) {
        const float* baseI = Wih + (sec * 256 + jbase + g) * 256 + sk * 32;
        const float* baseH = Whh + (sec * 256 + jbase + g) * 256 + sk * 32;
#pragma unroll
        for (int q = 0; q < 8; q++) {
            int qq = q ^ sk;
            ulonglong2 a = *(const ulonglong2*)(baseI + qq * 4);
            ulonglong2 b = *(const ulonglong2*)(baseH + qq * 4);
            ADD2(a.x, b.x);
            ADD2(a.y, b.y);
            wr[sec][q] = a;
        }
    }
    __syncthreads();
    cluster_sync_();

    // wait for feat from k1 (stale-pass on replays benign by determinism)
    if (tid == 0) {
        while ((atomicOr(&g_featflag, 0) & 0xFF) != 0xFF) __nanosleep(64);
    }
    __syncthreads();
    __threadfence();
    h_buf[0][tid] = g_feat[tid];
    __syncthreads();

    float c = 0.f;
    int par0 = 0, par1 = 0;

    // ---- step 0: gates = W_ih @ feat ----
    {
        unsigned long long a[4][2];
#pragma unroll
        for (int sec = 0; sec < 4; sec++) { a[sec][0] = 0ull; a[sec][1] = 0ull; }
        const ulonglong2* hb = (const ulonglong2*)(&h_buf[0][sk * 32]);
#pragma unroll
        for (int q = 0; q < 8; q++) {
            int qq = q ^ sk;
            ulonglong2 hx = hb[qq];
#pragma unroll
            for (int sec = 0; sec < 4; sec++) {
                ulonglong2 wv = *(const ulonglong2*)
                    (Wih + (sec * 256 + jbase + g) * 256 + sk * 32 + qq * 4);
                FMA2(a[sec][0], wv.x, hx.x);
                FMA2(a[sec][1], wv.y, hx.y);
            }
        }
        float fs[4];
#pragma unroll
        for (int sec = 0; sec < 4; sec++) {
            float l0, h0, l1, h1;
            UNPACK64(l0, h0, a[sec][0]);
            UNPACK64(l1, h1, a[sec][1]);
            fs[sec] = (l0 + h0) + (l1 + h1);
        }
#pragma unroll
        for (int m = 1; m < 8; m <<= 1)
#pragma unroll
            for (int sec = 0; sec < 4; sec++)
                fs[sec] += __shfl_xor_sync(0xffffffffu, fs[sec], m);
        float hval = 0.f;
        if (sk == 0) {
            float gi = fsig(fs[0] + bi[0]);
            float gf = fsig(fs[1] + bi[1]);
            float gg = ftanh_(fs[2] + bi[2]);
            float go = fsig(fs[3] + bi[3]);
            c = gf * c + gi * gg;
            hval = go * ftanh_(c);
            g_Ht[(jbase + g) * HT_STRIDE + 0] = hval;
        }
        float hhi = __shfl_down_sync(0xffffffffu, hval, 8);
        if ((tid & 15) == 0) {
            unsigned long long pk;
            PACK64(pk, hval, hhi);
            unsigned da = smem_u32(&h_buf[1][jbase + g]);
#pragma unroll
            for (int rk = 0; rk < 8; rk++) st_async_remote64(da, mb1, rk, pk);
        }
    }

    // ---- steps 1..100 ----
    for (int s = 1; s <= 100; s++) {
        int b = s & 1;
        unsigned mb = b ? mb1 : mb0;
        mbar_wait_cluster(mb, b ? par1 : par0);
        if (b) par1 ^= 1; else par0 ^= 1;
        if (tid == 0 && s <= 98) mbar_arrive_expect(mb, 1024);

        unsigned long long a[4][2];
#pragma unroll
        for (int sec = 0; sec < 4; sec++) { a[sec][0] = 0ull; a[sec][1] = 0ull; }
        const ulonglong2* hb = (const ulonglong2*)(&h_buf[b][sk * 32]);
#pragma unroll
        for (int q = 0; q < 8; q++) {
            ulonglong2 hx = hb[q ^ sk];
#pragma unroll
            for (int sec = 0; sec < 4; sec++) {
                FMA2(a[sec][0], wr[sec][q].x, hx.x);
                FMA2(a[sec][1], wr[sec][q].y, hx.y);
            }
        }
        float fs[4];
#pragma unroll
        for (int sec = 0; sec < 4; sec++) {
            float l0, h0, l1, h1;
            UNPACK64(l0, h0, a[sec][0]);
            UNPACK64(l1, h1, a[sec][1]);
            fs[sec] = (l0 + h0) + (l1 + h1);
        }
#pragma unroll
        for (int m = 1; m < 8; m <<= 1)
#pragma unroll
            for (int sec = 0; sec < 4; sec++)
                fs[sec] += __shfl_xor_sync(0xffffffffu, fs[sec], m);

        float hval = 0.f;
        if (sk == 0) {
            float gi = fsig(fs[0] + bi[0]);
            float gf = fsig(fs[1] + bi[1]);
            float gg = ftanh_(fs[2] + bi[2]);
            float go = fsig(fs[3] + bi[3]);
            c = gf * c + gi * gg;
            hval = go * ftanh_(c);
            g_Ht[(jbase + g) * HT_STRIDE + s] = hval;
        }
        if (s < 100) {
            float hhi = __shfl_down_sync(0xffffffffu, hval, 8);
            if ((tid & 15) == 0) {
                unsigned long long pk;
                PACK64(pk, hval, hhi);
                int nb = (s + 1) & 1;
                unsigned da = smem_u32(&h_buf[nb][jbase + g]);
                unsigned dm = nb ? mb1 : mb0;
#pragma unroll
                for (int rk = 0; rk < 8; rk++) st_async_remote64(da, dm, rk, pk);
            }
        }
        if (s == 25 || s == 51 || s == 77) {
            __syncthreads();
            if (tid == 0) {
                __threadfence();
                atomicAdd(&g_flag[s / 26], 1);
            }
        }
    }
    __syncthreads();
    if (tid == 0) {
        __threadfence();
        atomicAdd(&g_flag[3], 1);
    }
}

// ---------------- K3: decode (PDL secondary of K2) ----------------
__global__ void __launch_bounds__(256, 2)
k3_decode(const float* __restrict__ W_dec,
          const float* __restrict__ b_dec,
          float* __restrict__ out) {
    extern __shared__ __align__(16) float dsm[];
    float* Wb0 = dsm;
    float* Wb1 = dsm + 8192;
    unsigned long long* Hs = (unsigned long long*)(dsm + 16384);
    float* Hsf = dsm + 16384;

    int tid = threadIdx.x;
    int w = tid >> 5, lane = tid & 31;
    int vh = w & 1, kh = (w >> 1) & 1, rgrp = w >> 2;
    int vbase = blockIdx.x * 256;
    int yb = blockIdx.y;
    int rbase = yb * 26;
    int vg = vh * 32 + lane;
    int v0 = vbase + vg * 4;

    for (int i = tid; i < 8192; i += 256) Hsf[i] = 0.f;

#pragma unroll
    for (int b = 0; b < 2; b++) {
        int kc = 4 * b;
        float* W = b ? Wb1 : Wb0;
#pragma unroll
        for (int q = 0; q < 8; q++) {
            int F = tid + 256 * q;
            int vcol = F >> 3, kq = F & 7;
            int v = vbase + vcol; if (v >= VOCAB) v = VOCAB - 1;
            float4 x = *(const float4*)(W_dec + v * 256 + kc * 32 + kq * 4);
            int cs = vcol ^ (kq << 2);
            W[(kq * 4 + 0) * 256 + cs] = x.x;
            W[(kq * 4 + 1) * 256 + cs] = x.y;
            W[(kq * 4 + 2) * 256 + cs] = x.z;
            W[(kq * 4 + 3) * 256 + cs] = x.w;
        }
    }

    if (tid == 0) {
        while (atomicAdd(&g_flag[yb], 0) < NLSTM) __nanosleep(128);
    }
    __syncthreads();
    __threadfence();

    {
        int s = lane, kg = w;
        if (s < 26) {
            int rg2 = (s < 13) ? 0 : 1;
            int q = s - rg2 * 13;
            int row = rbase + s;
            bool ok = (row < ROWS_OUT);
#pragma unroll
            for (int t = 0; t < 32; t++) {
                int k = kg + 8 * t;
                float h = ok ? __ldcg(g_Ht + k * HT_STRIDE + row) : 0.f;
                Hsf[(k * 16 + rg2 * 8) * 2 + q] = h;
            }
        }
    }
    __syncthreads();

    unsigned long long acc[7][4];
#pragma unroll
    for (int p2 = 0; p2 < 7; p2++)
#pragma unroll
        for (int c2 = 0; c2 < 4; c2++) acc[p2][c2] = 0ull;

    const float* Wmy = kh ? Wb1 : Wb0;

    for (int i = 0; i < 4; i++) {
        int kc = i + 4 * kh;
#pragma unroll
        for (int kk = 0; kk < 32; kk++) {
            float4 wq = *(const float4*)(Wmy + kk * 256 + ((vg ^ (kk >> 2)) << 2));
            unsigned long long wd0, wd1, wd2, wd3;
            DUP2(wd0, wq.x); DUP2(wd1, wq.y); DUP2(wd2, wq.z); DUP2(wd3, wq.w);
            const unsigned long long* hp = Hs + (kc * 32 + kk) * 16 + rgrp * 8;
            ulonglong2 hA = *(const ulonglong2*)hp;
            ulonglong2 hB = *(const ulonglong2*)(hp + 2);
            ulonglong2 hC = *(const ulonglong2*)(hp + 4);
            unsigned long long hD = hp[6];
            FMA2(acc[0][0], hA.x, wd0); FMA2(acc[0][1], hA.x, wd1);
            FMA2(acc[0][2], hA.x, wd2); FMA2(acc[0][3], hA.x, wd3);
            FMA2(acc[1][0], hA.y, wd0); FMA2(acc[1][1], hA.y, wd1);
            FMA2(acc[1][2], hA.y, wd2); FMA2(acc[1][3], hA.y, wd3);
            FMA2(acc[2][0], hB.x, wd0); FMA2(acc[2][1], hB.x, wd1);
            FMA2(acc[2][2], hB.x, wd2); FMA2(acc[2][3], hB.x, wd3);
            FMA2(acc[3][0], hB.y, wd0); FMA2(acc[3][1], hB.y, wd1);
            FMA2(acc[3][2], hB.y, wd2); FMA2(acc[3][3], hB.y, wd3);
            FMA2(acc[4][0], hC.x, wd0); FMA2(acc[4][1], hC.x, wd1);
            FMA2(acc[4][2], hC.x, wd2); FMA2(acc[4][3], hC.x, wd3);
            FMA2(acc[5][0], hC.y, wd0); FMA2(acc[5][1], hC.y, wd1);
            FMA2(acc[5][2], hC.y, wd2); FMA2(acc[5][3], hC.y, wd3);
            FMA2(acc[6][0], hD, wd0);   FMA2(acc[6][1], hD, wd1);
            FMA2(acc[6][2], hD, wd2);   FMA2(acc[6][3], hD, wd3);
        }
        __syncthreads();
        if (i < 3) {
#pragma unroll
            for (int b = 0; b < 2; b++) {
                int kcn = (i + 1) + 4 * b;
                float* W = b ? Wb1 : Wb0;
#pragma unroll
                for (int q = 0; q < 8; q++) {
                    int F = tid + 256 * q;
                    int vcol = F >> 3, kq = F & 7;
                    int v = vbase + vcol; if (v >= VOCAB) v = VOCAB - 1;
                    float4 x = *(const float4*)(W_dec + v * 256 + kcn * 32 + kq * 4);
                    int cs = vcol ^ (kq << 2);
                    W[(kq * 4 + 0) * 256 + cs] = x.x;
                    W[(kq * 4 + 1) * 256 + cs] = x.y;
                    W[(kq * 4 + 2) * 256 + cs] = x.z;
                    W[(kq * 4 + 3) * 256 + cs] = x.w;
                }
            }
            __syncthreads();
        }
    }

    unsigned long long* red = (unsigned long long*)dsm;
    int slot = (rgrp * 2 + vh) * 32 + lane;
    __syncthreads();
    if (kh == 1) {
#pragma unroll
        for (int p2 = 0; p2 < 7; p2++)
#pragma unroll
            for (int c2 = 0; c2 < 4; c2++)
                red[(p2 * 4 + c2) * 128 + slot] = acc[p2][c2];
    }
    __syncthreads();
    if (kh == 0) {
#pragma unroll
        for (int p2 = 0; p2 < 7; p2++)
#pragma unroll
            for (int c2 = 0; c2 < 4; c2++)
                ADD2(acc[p2][c2], red[(p2 * 4 + c2) * 128 + slot]);

        if (v0 < VOCAB) {
            float4 bv = *(const float4*)(b_dec + v0);
#pragma unroll
            for (int p2 = 0; p2 < 7; p2++) {
                int r0 = rbase + rgrp * 13 + 2 * p2;
                float lo0, hi0, lo1, hi1, lo2, hi2, lo3, hi3;
                UNPACK64(lo0, hi0, acc[p2][0]);
                UNPACK64(lo1, hi1, acc[p2][1]);
                UNPACK64(lo2, hi2, acc[p2][2]);
                UNPACK64(lo3, hi3, acc[p2][3]);
                if (r0 < ROWS_OUT) {
                    float4 o;
                    o.x = fmaxf(lo0 + bv.x, 0.f);
                    o.y = fmaxf(lo1 + bv.y, 0.f);
                    o.z = fmaxf(lo2 + bv.z, 0.f);
                    o.w = fmaxf(lo3 + bv.w, 0.f);
                    *(float4*)(out + r0 * VOCAB + v0) = o;
                }
                if (p2 < 6 && r0 + 1 < ROWS_OUT) {
                    float4 o;
                    o.x = fmaxf(hi0 + bv.x, 0.f);
                    o.y = fmaxf(hi1 + bv.y, 0.f);
                    o.z = fmaxf(hi2 + bv.z, 0.f);
                    o.w = fmaxf(hi3 + bv.w, 0.f);
                    *(float4*)(out + (r0 + 1) * VOCAB + v0) = o;
                }
            }
        }
    }
}

// ---------------- launch ----------------
extern "C" void kernel_launch(void* const* d_in, const int* in_sizes, int n_in,
                              void* d_out, int out_size) {
    const float* board    = (const float*)d_in[0];
    const float* conv_w   = (const float*)d_in[1];
    const float* conv_b   = (const float*)d_in[2];
    const float* bn_gamma = (const float*)d_in[3];
    const float* bn_beta  = (const float*)d_in[4];
    const float* p        = (const float*)d_in[5];
    const float* W_lin    = (const float*)d_in[6];
    const float* b_lin    = (const float*)d_in[7];
    const float* W_ih     = (const float*)d_in[8];
    const float* b_ih     = (const float*)d_in[9];
    const float* W_hh     = (const float*)d_in[10];
    const float* b_hh     = (const float*)d_in[11];
    const float* W_dec    = (const float*)d_in[12];
    const float* b_dec    = (const float*)d_in[13];
    float* out = (float*)d_out;

    const int K1_SMEM = (384 + 32 * 361) * 4;
    const int K2_PAD_SMEM = 184320;
    const int K3_SMEM = 98304;
    cudaFuncSetAttribute(k1_prep, cudaFuncAttributeMaxDynamicSharedMemorySize, K1_SMEM);
    cudaFuncSetAttribute(k2_lstm, cudaFuncAttributeMaxDynamicSharedMemorySize, K2_PAD_SMEM);
    cudaFuncSetAttribute(k3_decode, cudaFuncAttributeMaxDynamicSharedMemorySize, K3_SMEM);

    k1_prep<<<9, 512, K1_SMEM>>>(board, conv_w, conv_b, bn_gamma, bn_beta, p, W_lin, b_lin);

    // K2: PDL secondary of k1 — weight load overlaps conv/feat
    {
        cudaLaunchConfig_t cfg = {};
        cfg.gridDim = dim3(8, 1, 1);
        cfg.blockDim = dim3(256, 1, 1);
        cfg.dynamicSmemBytes = K2_PAD_SMEM;
        cfg.stream = 0;
        cudaLaunchAttribute at[1];
        at[0].id = cudaLaunchAttributeProgrammaticStreamSerialization;
        at[0].val.programmaticStreamSerializationAllowed = 1;
        cfg.attrs = at;
        cfg.numAttrs = 1;
        cudaLaunchKernelEx(&cfg, k2_lstm, W_ih, W_hh, b_ih, b_hh);
    }

    // K3: PDL secondary of K2 — overlaps the recurrence
    {
        cudaLaunchConfig_t cfg = {};
        cfg.gridDim = dim3(NXT, NY, 1);
        cfg.blockDim = dim3(256, 1, 1);
        cfg.dynamicSmemBytes = K3_SMEM;
        cfg.stream = 0;
        cudaLaunchAttribute at[1];
        at[0].id = cudaLaunchAttributeProgrammaticStreamSerialization;
        at[0].val.programmaticStreamSerializationAllowed = 1;
        cfg.attrs = at;
        cfg.numAttrs = 1;
        cudaLaunchKernelEx(&cfg, k3_decode, W_dec, b_dec, out);
    }
}